// round 8
// baseline (speedup 1.0000x reference)
#include <cuda_runtime.h>

#define NB 16
#define TQ 256
#define TK 256
#define DD 256
#define FF 36
#define HH 8
#define DK 32
#define SFD 6

// Scratch (allocation-free rule: __device__ globals)
__device__ float g_Q[NB*TQ*DD];        // [b][q][h*DK+j]
__device__ float g_K[NB*TK*DD];        // [b][k][h*DK+j]
__device__ float g_HN[NB*TQ*FF*HH];    // [b][q][f][h]

// ---------------------------------------------------------------------------
// Packed fp32x2 helpers (sm_103a: FFMA2 via PTX only)
// ---------------------------------------------------------------------------
__device__ __forceinline__ float2 fma2(float2 a, float2 b, float2 c) {
    float2 d;
    asm("fma.rn.f32x2 %0, %1, %2, %3;"
        : "=l"(reinterpret_cast<unsigned long long&>(d))
        : "l"(reinterpret_cast<unsigned long long&>(a)),
          "l"(reinterpret_cast<unsigned long long&>(b)),
          "l"(reinterpret_cast<unsigned long long&>(c)));
    return d;
}
__device__ __forceinline__ float2 dup2(float s) { return make_float2(s, s); }
__device__ __forceinline__ float2 tanh2(float2 a) {
    float2 r;
    asm("tanh.approx.f32 %0, %1;" : "=f"(r.x) : "f"(a.x));
    asm("tanh.approx.f32 %0, %1;" : "=f"(r.y) : "f"(a.y));
    return r;
}

// ---------------------------------------------------------------------------
// Kernel 1: head projections as register-tiled SGEMM, tile 64x128.
// out[n, h*32+j] = sum_d x[n,d] * W[h,d,j] == X(4096x256) @ Wbig(256x256) x2.
// 256 threads, thread owns 4 rows x 8 cols: 16 FFMA2 vs 4 LDS.128 per kk.
// ~75 regs -> 3 blocks/SM (24 warps). Grid 256 = one balanced wave.
// ---------------------------------------------------------------------------
#define QM 64
#define QN 128
#define QKT 16

__global__ void __launch_bounds__(256) proj_kernel(
        const float* __restrict__ query, const float* __restrict__ key,
        const float* __restrict__ Wq,    const float* __restrict__ Wk) {
    __shared__ __align__(16) float As[QKT][2*QM + 4];   // [kk][2n] duplicated rows
    __shared__ __align__(16) float Bs[QKT][QN + 4];     // [kk][c]

    int n0 = blockIdx.x * QM;
    int c0 = blockIdx.y * QN;
    int which = blockIdx.z;
    const float* x = which ? key : query;
    const float* W = which ? Wk : Wq;

    int t  = threadIdx.x;
    int tm = t >> 4;          // 0..15: rows 4tm..4tm+3
    int tn = t & 15;          // cols 8tn..8tn+7

    // fill-index precompute
    int fa_n  = t >> 2;                 // A fill: row 0..63
    int fa_k  = (t & 3) * 4;            //   k offsets (1 float4)
    int fb_kk = t >> 4;                 // B fill: kk row 0..15
    int fb_cq = (t & 15) * 8;           //   col offset (2 float4)
    int fb_h  = (c0 + fb_cq) >> 5;
    int fb_j  = (c0 + fb_cq) & 31;

    float2 acc[4][4];
#pragma unroll
    for (int r = 0; r < 4; ++r)
#pragma unroll
        for (int p = 0; p < 4; ++p) acc[r][p] = make_float2(0.f, 0.f);

    // ---- prefetch tile 0 into registers
    float4 pa, pb0, pb1;
    {
        pa  = *(const float4*)(x + (size_t)(n0 + fa_n)*DD + fa_k);
        const float* wr = W + ((size_t)fb_h*DD + fb_kk)*DK + fb_j;
        pb0 = *(const float4*)(wr);
        pb1 = *(const float4*)(wr + 4);
    }

#pragma unroll 1
    for (int kt = 0; kt < DD; kt += QKT) {
        // ---- store prefetched regs to smem (A duplicated for FFMA2)
        *(float2*)(&As[fa_k+0][2*fa_n]) = dup2(pa.x);
        *(float2*)(&As[fa_k+1][2*fa_n]) = dup2(pa.y);
        *(float2*)(&As[fa_k+2][2*fa_n]) = dup2(pa.z);
        *(float2*)(&As[fa_k+3][2*fa_n]) = dup2(pa.w);
        *(float4*)(&Bs[fb_kk][fb_cq])     = pb0;
        *(float4*)(&Bs[fb_kk][fb_cq + 4]) = pb1;
        __syncthreads();

        // ---- prefetch next tile (overlaps compute)
        if (kt + QKT < DD) {
            pa  = *(const float4*)(x + (size_t)(n0 + fa_n)*DD + kt + QKT + fa_k);
            const float* wr = W + ((size_t)fb_h*DD + kt + QKT + fb_kk)*DK + fb_j;
            pb0 = *(const float4*)(wr);
            pb1 = *(const float4*)(wr + 4);
        }

        // ---- compute: per kk, 4 LDS.128 feed 16 FFMA2
#pragma unroll
        for (int kk = 0; kk < QKT; ++kk) {
            float2 a[4], bv[4];
            *(float4*)&a[0]  = *(const float4*)&As[kk][8*tm];
            *(float4*)&a[2]  = *(const float4*)&As[kk][8*tm + 4];
            *(float4*)&bv[0] = *(const float4*)&Bs[kk][8*tn];
            *(float4*)&bv[2] = *(const float4*)&Bs[kk][8*tn + 4];
#pragma unroll
            for (int r = 0; r < 4; ++r)
#pragma unroll
                for (int p = 0; p < 4; ++p)
                    acc[r][p] = fma2(a[r], bv[p], acc[r][p]);
        }
        __syncthreads();
    }

    // ---- write out: rows n0+4tm+r, cols c0+8tn..+7 (2 STG.128 per row)
    float* out = which ? g_K : g_Q;
#pragma unroll
    for (int r = 0; r < 4; ++r) {
        int n = n0 + 4*tm + r;
        float4 lo, hi;
        *(float2*)&lo.x = acc[r][0];
        *(float2*)&lo.z = acc[r][1];
        *(float2*)&hi.x = acc[r][2];
        *(float2*)&hi.z = acc[r][3];
        *(float4*)(out + (size_t)n*DD + c0 + 8*tn)     = lo;
        *(float4*)(out + (size_t)n*DD + c0 + 8*tn + 4) = hi;
    }
}

// ---------------------------------------------------------------------------
// Kernel 2 (fused score+apply): per (b, h, qtile-64) block, loop k-tiles of 32.
// Phase A: E (duplicated pairs) into smem. Phase B: accumulate num/den.
// Es stored dup'd [kk][2q] so Phase B's e-pair is one LDS.128 (no dup MOVs).
// ---------------------------------------------------------------------------
__global__ void __launch_bounds__(128, 4) fused_attn_kernel(
        const float* __restrict__ value, const float* __restrict__ mask) {
    int b = blockIdx.x, h = blockIdx.y;
    int q0 = blockIdx.z * 64;
    int t = threadIdx.x;

    __shared__ __align__(16) float Qst[32][68];     // [j][q] transposed Q tile
    __shared__ __align__(16) float Ksd[32][66];     // [kk][2j] duplicated K tile
    __shared__ __align__(16) float Es[32][136];     // [kk][2q] duplicated E
    __shared__ __align__(16) float Cs[32][4][20];   // [kk][fg][(mv,m)x9 + pad]

    // Load Q tile transposed (once per block)
    for (int i = t; i < 64*32; i += 128) {
        int q = i >> 5, j = i & 31;
        Qst[j][q] = g_Q[(size_t)(b*TQ + q0 + q)*DD + h*DK + j];
    }

    // Phase B mapping
    int qg = t >> 2;            // q local = qg*2 + qq
    int fg = t & 3;             // f = fg*9 + i
    // Phase A mapping
    int kkA = t & 31;
    int qq4 = t >> 5;           // 16-q chunk

    float2 nd[2][9];
#pragma unroll
    for (int qq = 0; qq < 2; ++qq)
#pragma unroll
        for (int i = 0; i < 9; ++i) nd[qq][i] = make_float2(0.f, 0.f);

#pragma unroll 1
    for (int kt = 0; kt < TK; kt += 32) {
        __syncthreads();   // previous iteration's readers of Ksd/Cs done
        // K tile fill, duplicated for FFMA2: 32kk x 32j, 8 per thread
#pragma unroll
        for (int r = 0; r < 8; ++r) {
            int i = t + r*128;
            int kk = i >> 5, j = i & 31;
            float kv = g_K[(size_t)(b*TK + kt + kk)*DD + h*DK + j];
            *(float2*)&Ksd[kk][2*j] = make_float2(kv, kv);
        }
        // Cs fill: 32k x 9 float4-groups over f
        for (int i = t; i < 288; i += 128) {
            int k = i / 9;
            int c4 = (i - k*9) * 4;
            size_t base = (size_t)(b*TK + kt + k)*FF + c4;
            float4 mm = *(const float4*)(mask + base);
            float4 vv = *(const float4*)(value + base);
#pragma unroll
            for (int u = 0; u < 4; ++u) {
                int f = c4 + u;
                int g = f / 9, ii = f - g*9;
                float m = (&mm.x)[u], v = (&vv.x)[u];
                Cs[k][g][2*ii]   = m * v;
                Cs[k][g][2*ii+1] = m;
            }
        }
        __syncthreads();

        // ---- Phase A: thread owns kk = kkA, computes 16 q's (qq4*16..+15)
        {
            float2 acc2[8];
#pragma unroll
            for (int p = 0; p < 8; ++p) acc2[p] = make_float2(0.f, 0.f);
#pragma unroll
            for (int jc = 0; jc < 4; ++jc) {      // 8 j at a time (reg-lean)
                float2 kr2[8];
#pragma unroll
                for (int j = 0; j < 8; ++j)
                    kr2[j] = *(const float2*)&Ksd[kkA][2*(jc*8 + j)];
#pragma unroll
                for (int j = 0; j < 8; ++j) {
                    const float4* qp = (const float4*)&Qst[jc*8 + j][qq4*16];
#pragma unroll
                    for (int c = 0; c < 4; ++c) {
                        float4 qv = qp[c];
                        acc2[2*c]   = fma2(*(const float2*)&qv.x, kr2[j], acc2[2*c]);
                        acc2[2*c+1] = fma2(*(const float2*)&qv.z, kr2[j], acc2[2*c+1]);
                    }
                }
            }
            // store duplicated E pairs: per 4-q group, 2 STS.128
#pragma unroll
            for (int c = 0; c < 4; ++c) {
                float e0 = __expf(fminf(acc2[2*c].x,   80.f));
                float e1 = __expf(fminf(acc2[2*c].y,   80.f));
                float e2 = __expf(fminf(acc2[2*c+1].x, 80.f));
                float e3 = __expf(fminf(acc2[2*c+1].y, 80.f));
                int qb = qq4*16 + 4*c;
                float4 lo, hi;
                lo.x = e0; lo.y = e0; lo.z = e1; lo.w = e1;
                hi.x = e2; hi.y = e2; hi.z = e3; hi.w = e3;
                *(float4*)&Es[kkA][2*qb]     = lo;
                *(float4*)&Es[kkA][2*qb + 4] = hi;
            }
        }
        __syncthreads();

        // ---- Phase B: accumulate num/den (e-pair = 1 LDS.128, dup'd)
#pragma unroll 4
        for (int kk = 0; kk < 32; ++kk) {
            float4 e01 = *(const float4*)&Es[kk][4*qg];
            float2 e0 = *(const float2*)&e01.x;
            float2 e1 = *(const float2*)&e01.z;
            const float4* cp = (const float4*)&Cs[kk][fg][0];
            float4 c0 = cp[0], c1 = cp[1], c2 = cp[2], c3 = cp[3], c4v = cp[4];
            nd[0][0] = fma2(e0, *(const float2*)&c0.x,  nd[0][0]);
            nd[1][0] = fma2(e1, *(const float2*)&c0.x,  nd[1][0]);
            nd[0][1] = fma2(e0, *(const float2*)&c0.z,  nd[0][1]);
            nd[1][1] = fma2(e1, *(const float2*)&c0.z,  nd[1][1]);
            nd[0][2] = fma2(e0, *(const float2*)&c1.x,  nd[0][2]);
            nd[1][2] = fma2(e1, *(const float2*)&c1.x,  nd[1][2]);
            nd[0][3] = fma2(e0, *(const float2*)&c1.z,  nd[0][3]);
            nd[1][3] = fma2(e1, *(const float2*)&c1.z,  nd[1][3]);
            nd[0][4] = fma2(e0, *(const float2*)&c2.x,  nd[0][4]);
            nd[1][4] = fma2(e1, *(const float2*)&c2.x,  nd[1][4]);
            nd[0][5] = fma2(e0, *(const float2*)&c2.z,  nd[0][5]);
            nd[1][5] = fma2(e1, *(const float2*)&c2.z,  nd[1][5]);
            nd[0][6] = fma2(e0, *(const float2*)&c3.x,  nd[0][6]);
            nd[1][6] = fma2(e1, *(const float2*)&c3.x,  nd[1][6]);
            nd[0][7] = fma2(e0, *(const float2*)&c3.z,  nd[0][7]);
            nd[1][7] = fma2(e1, *(const float2*)&c3.z,  nd[1][7]);
            nd[0][8] = fma2(e0, *(const float2*)&c4v.x, nd[0][8]);
            nd[1][8] = fma2(e1, *(const float2*)&c4v.x, nd[1][8]);
        }
    }

#pragma unroll
    for (int qq = 0; qq < 2; ++qq) {
        int q = q0 + qg*2 + qq;
        float* o = g_HN + (size_t)(b*TQ + q)*FF*HH + h;
#pragma unroll
        for (int i = 0; i < 9; ++i) {
            int f = fg*9 + i;
            o[(size_t)f*HH] = __fdividef(nd[qq][i].x, nd[qq][i].y);
        }
    }
}

// ---------------------------------------------------------------------------
// Kernel 3: fused epilogue. Block = 2 (b,q) rows; 64 threads per row; thread
// owns 4 d's = two FFMA2 pairs.
// ---------------------------------------------------------------------------
__global__ void __launch_bounds__(128) epilogue_kernel(
        const float* __restrict__ Wc,  const float* __restrict__ bc,
        const float* __restrict__ Wo1, const float* __restrict__ bo1,
        const float* __restrict__ Wo2, const float* __restrict__ bo2,
        float* __restrict__ out) {
    int t    = threadIdx.x;
    int half = t >> 6;           // which bq of the pair
    int u    = t & 63;           // d base
    int bq   = 2*blockIdx.x + half;

    __shared__ __align__(16) float2 hs2[2][FF*HH];   // duplicated pairs, per bq
    __shared__ __align__(16) float2 w12[FF*SFD];

    const float* hn0 = g_HN + (size_t)(2*blockIdx.x)*FF*HH;
    for (int i = t; i < 144; i += 128) {        // 2 x 72 float4
        int which = i / 72, r = i - which*72;
        float4 v = *(const float4*)(hn0 + (size_t)which*FF*HH + 4*r);
        float2* dst = &hs2[which][4*r];
        dst[0] = dup2(v.x); dst[1] = dup2(v.y);
        dst[2] = dup2(v.z); dst[3] = dup2(v.w);
    }
    if (t < 54) {                                // 54 float4 = 216 floats
        float4 v = *(const float4*)(Wo1 + 4*t);
        w12[4*t+0] = dup2(v.x); w12[4*t+1] = dup2(v.y);
        w12[4*t+2] = dup2(v.z); w12[4*t+3] = dup2(v.w);
    }
    __syncthreads();

    int d0 = u, d1 = u + 64, d2 = u + 128, d3 = u + 192;
    float2 wcA[HH], wcB[HH];
#pragma unroll
    for (int h = 0; h < HH; ++h) {
        wcA[h] = make_float2(Wc[h*DD + d0], Wc[h*DD + d1]);
        wcB[h] = make_float2(Wc[h*DD + d2], Wc[h*DD + d3]);
    }
    float2 bcA = make_float2(bc[d0], bc[d1]);
    float2 bcB = make_float2(bc[d2], bc[d3]);

    float2 accA[SFD], accB[SFD];
#pragma unroll
    for (int s = 0; s < SFD; ++s) { accA[s] = dup2(bo1[s]); accB[s] = dup2(bo1[s]); }

    const float2* hbase = &hs2[half][0];
#pragma unroll 4
    for (int f = 0; f < FF; ++f) {
        const float4* hp = (const float4*)&hbase[f*HH];   // 8 float2, 16B aligned
        float2 aA = bcA, aB = bcB;
#pragma unroll
        for (int j = 0; j < 4; ++j) {
            float4 hv = hp[j];
            float2 lo = *(const float2*)&hv.x;
            float2 hi = *(const float2*)&hv.z;
            aA = fma2(lo, wcA[2*j],   aA);
            aA = fma2(hi, wcA[2*j+1], aA);
            aB = fma2(lo, wcB[2*j],   aB);
            aB = fma2(hi, wcB[2*j+1], aB);
        }
        float2 latA = tanh2(aA), latB = tanh2(aB);
        const float4* wp = (const float4*)&w12[f*SFD];    // 6 float2, 16B aligned
#pragma unroll
        for (int j = 0; j < 3; ++j) {
            float4 wv = wp[j];
            float2 lo = *(const float2*)&wv.x;
            float2 hi = *(const float2*)&wv.z;
            accA[2*j]   = fma2(latA, lo, accA[2*j]);
            accA[2*j+1] = fma2(latA, hi, accA[2*j+1]);
            accB[2*j]   = fma2(latB, lo, accB[2*j]);
            accB[2*j+1] = fma2(latB, hi, accB[2*j+1]);
        }
    }

    float2 resA = make_float2(bo2[d0], bo2[d1]);
    float2 resB = make_float2(bo2[d2], bo2[d3]);
#pragma unroll
    for (int s = 0; s < SFD; ++s) {
        float2 w2 = dup2(Wo2[s]);
        resA = fma2(tanh2(accA[s]), w2, resA);
        resB = fma2(tanh2(accB[s]), w2, resB);
    }

    float* o = out + (size_t)bq*DD;
    o[d0] = resA.x; o[d1] = resA.y;
    o[d2] = resB.x; o[d3] = resB.y;
}

// ---------------------------------------------------------------------------
extern "C" void kernel_launch(void* const* d_in, const int* in_sizes, int n_in,
                              void* d_out, int out_size) {
    const float* query = (const float*)d_in[0];
    const float* key   = (const float*)d_in[1];
    const float* value = (const float*)d_in[2];
    const float* mask  = (const float*)d_in[3];
    const float* Wq    = (const float*)d_in[4];
    const float* Wk    = (const float*)d_in[5];
    const float* Wc    = (const float*)d_in[6];
    const float* bc    = (const float*)d_in[7];
    const float* Wo1   = (const float*)d_in[8];
    const float* bo1   = (const float*)d_in[9];
    const float* Wo2   = (const float*)d_in[10];
    const float* bo2   = (const float*)d_in[11];
    float* out = (float*)d_out;

    proj_kernel<<<dim3(NB*TQ/QM, DD/QN, 2), 256>>>(query, key, Wq, Wk);
    fused_attn_kernel<<<dim3(NB, HH, 4), 128>>>(value, mask);
    epilogue_kernel<<<NB*TQ/2, 128>>>(Wc, bc, Wo1, bo1, Wo2, bo2, out);
}

// round 9
// speedup vs baseline: 1.2619x; 1.2619x over previous
#include <cuda_runtime.h>

#define NB 16
#define TQ 256
#define TK 256
#define DD 256
#define FF 36
#define HH 8
#define DK 32
#define SFD 6

// Scratch (allocation-free rule: __device__ globals)
__device__ float g_Q[NB*TQ*DD];        // [b][q][h*DK+j]
__device__ float g_K[NB*TK*DD];        // [b][k][h*DK+j]
__device__ float g_HN[NB*TQ*FF*HH];    // [b][q][f][h]

// ---------------------------------------------------------------------------
// Packed fp32x2 helpers (sm_103a: FFMA2 via PTX only)
// ---------------------------------------------------------------------------
__device__ __forceinline__ float2 fma2(float2 a, float2 b, float2 c) {
    float2 d;
    asm("fma.rn.f32x2 %0, %1, %2, %3;"
        : "=l"(reinterpret_cast<unsigned long long&>(d))
        : "l"(reinterpret_cast<unsigned long long&>(a)),
          "l"(reinterpret_cast<unsigned long long&>(b)),
          "l"(reinterpret_cast<unsigned long long&>(c)));
    return d;
}
__device__ __forceinline__ float2 dup2(float s) { return make_float2(s, s); }
__device__ __forceinline__ float2 tanh2(float2 a) {
    float2 r;
    asm("tanh.approx.f32 %0, %1;" : "=f"(r.x) : "f"(a.x));
    asm("tanh.approx.f32 %0, %1;" : "=f"(r.y) : "f"(a.y));
    return r;
}

// ---------------------------------------------------------------------------
// Kernel 1: head projections as register-tiled SGEMM, tile 128x128.
// A tile NON-duplicated in smem (crossbar bytes halved vs R7); FFMA2 dup
// pairs built via register MOVs on the idle ALU pipe.
// Per kk per warp: 4 LDS.128 (2KB) vs 32 FFMA2 (16 cyc) -> balanced.
// ---------------------------------------------------------------------------
#define PM 128
#define PN 128
#define PKT 16

__global__ void __launch_bounds__(256) proj_kernel(
        const float* __restrict__ query, const float* __restrict__ key,
        const float* __restrict__ Wq,    const float* __restrict__ Wk) {
    __shared__ __align__(16) float As[PKT][PM + 4];     // [kk][n] plain
    __shared__ __align__(16) float Bs[PKT][PN + 4];     // [kk][c]

    int n0 = blockIdx.x * PM;
    int c0 = blockIdx.y * PN;
    int which = blockIdx.z;
    const float* x = which ? key : query;
    const float* W = which ? Wk : Wq;

    int t  = threadIdx.x;
    int tn = t & 15;          // col quad: c0 + 4tn (+64)
    int tm = t >> 4;          // row quad: n0 + 4tm (+64)

    // fill-index precompute
    int fa_n  = t >> 1;                 // A fill: row 0..127
    int fa_c4 = (t & 1) * 8;            //   k offsets 0..7 / 8..15
    int fb_kk = t >> 5;                 // B fill: kk row (0..7, +8)
    int fb_cq = (t & 31) * 4;           //   col quad
    int fb_h  = (c0 + fb_cq) >> 5;
    int fb_j  = (c0 + fb_cq) & 31;

    float2 acc[8][4];
#pragma unroll
    for (int r = 0; r < 8; ++r)
#pragma unroll
        for (int p = 0; p < 4; ++p) acc[r][p] = make_float2(0.f, 0.f);

    // ---- prefetch tile 0 into registers
    float4 pa0, pa1, pb0, pb1;
    {
        const float* xr = x + (size_t)(n0 + fa_n)*DD + fa_c4;
        pa0 = *(const float4*)(xr);
        pa1 = *(const float4*)(xr + 4);
        const float* wr = W + ((size_t)fb_h*DD + fb_kk)*DK + fb_j;
        pb0 = *(const float4*)(wr);
        pb1 = *(const float4*)(wr + 8*DK);
    }

#pragma unroll 1
    for (int kt = 0; kt < DD; kt += PKT) {
        // ---- store prefetched regs to smem (A transposed, non-dup)
        As[fa_c4+0][fa_n] = pa0.x;
        As[fa_c4+1][fa_n] = pa0.y;
        As[fa_c4+2][fa_n] = pa0.z;
        As[fa_c4+3][fa_n] = pa0.w;
        As[fa_c4+4][fa_n] = pa1.x;
        As[fa_c4+5][fa_n] = pa1.y;
        As[fa_c4+6][fa_n] = pa1.z;
        As[fa_c4+7][fa_n] = pa1.w;
        *(float4*)(&Bs[fb_kk  ][fb_cq]) = pb0;
        *(float4*)(&Bs[fb_kk+8][fb_cq]) = pb1;
        __syncthreads();

        // ---- prefetch next tile (overlaps compute)
        if (kt + PKT < DD) {
            const float* xr = x + (size_t)(n0 + fa_n)*DD + kt + PKT + fa_c4;
            pa0 = *(const float4*)(xr);
            pa1 = *(const float4*)(xr + 4);
            const float* wr = W + ((size_t)fb_h*DD + kt + PKT + fb_kk)*DK + fb_j;
            pb0 = *(const float4*)(wr);
            pb1 = *(const float4*)(wr + 8*DK);
        }

        // ---- compute: per kk, 4 LDS.128 + 8 reg-dups feed 32 FFMA2
#pragma unroll
        for (int kk = 0; kk < PKT; ++kk) {
            float4 alo = *(const float4*)&As[kk][4*tm];        // rows 4tm..+3
            float4 ahi = *(const float4*)&As[kk][4*tm + 64];   // rows +64
            float4 b0  = *(const float4*)&Bs[kk][4*tn];
            float4 b1  = *(const float4*)&Bs[kk][4*tn + 64];
            float2 a[8];
            a[0] = dup2(alo.x); a[1] = dup2(alo.y);
            a[2] = dup2(alo.z); a[3] = dup2(alo.w);
            a[4] = dup2(ahi.x); a[5] = dup2(ahi.y);
            a[6] = dup2(ahi.z); a[7] = dup2(ahi.w);
            float2 bv[4];
            bv[0] = *(const float2*)&b0.x;
            bv[1] = *(const float2*)&b0.z;
            bv[2] = *(const float2*)&b1.x;
            bv[3] = *(const float2*)&b1.z;
#pragma unroll
            for (int r = 0; r < 8; ++r)
#pragma unroll
                for (int p = 0; p < 4; ++p)
                    acc[r][p] = fma2(a[r], bv[p], acc[r][p]);
        }
        __syncthreads();
    }

    // ---- write out: rows 4tm+(r>>2)*64+(r&3), col quads c0+4tn (+64)
    float* out = which ? g_K : g_Q;
#pragma unroll
    for (int r = 0; r < 8; ++r) {
        int n = n0 + 4*tm + (r >> 2)*64 + (r & 3);
        float4 lo, hi;
        *(float2*)&lo.x = acc[r][0];
        *(float2*)&lo.z = acc[r][1];
        *(float2*)&hi.x = acc[r][2];
        *(float2*)&hi.z = acc[r][3];
        *(float4*)(out + (size_t)n*DD + c0 + 4*tn)      = lo;
        *(float4*)(out + (size_t)n*DD + c0 + 4*tn + 64) = hi;
    }
}

// ---------------------------------------------------------------------------
// Kernel 2 (fused score+apply): per (b, h, qtile-64) block, loop k-tiles of 32.
// Phase A: E[kk][q] = exp(Q.K) into smem. Phase B: accumulate num/den.
// (R7 version.)
// ---------------------------------------------------------------------------
__global__ void __launch_bounds__(128, 4) fused_attn_kernel(
        const float* __restrict__ value, const float* __restrict__ mask) {
    int b = blockIdx.x, h = blockIdx.y;
    int q0 = blockIdx.z * 64;
    int t = threadIdx.x;

    __shared__ __align__(16) float Qst[32][68];     // [j][q] transposed Q tile
    __shared__ __align__(16) float Ksd[32][66];     // [kk][2j] duplicated K tile
    __shared__ __align__(16) float Es[32][68];      // [kk][q]
    __shared__ __align__(16) float Cs[32][4][20];   // [kk][fg][(mv,m)x9 + pad]

    // Load Q tile transposed (once per block)
    for (int i = t; i < 64*32; i += 128) {
        int q = i >> 5, j = i & 31;
        Qst[j][q] = g_Q[(size_t)(b*TQ + q0 + q)*DD + h*DK + j];
    }

    // Phase B mapping
    int qg = t >> 2;            // q local = qg*2 + qq
    int fg = t & 3;             // f = fg*9 + i
    // Phase A mapping
    int kkA = t & 31;
    int qq4 = t >> 5;           // 16-q chunk

    float2 nd[2][9];
#pragma unroll
    for (int qq = 0; qq < 2; ++qq)
#pragma unroll
        for (int i = 0; i < 9; ++i) nd[qq][i] = make_float2(0.f, 0.f);

#pragma unroll 1
    for (int kt = 0; kt < TK; kt += 32) {
        __syncthreads();   // previous iteration's readers of Ksd/Cs done
        // K tile fill, duplicated for FFMA2: 32kk x 32j, 8 per thread
#pragma unroll
        for (int r = 0; r < 8; ++r) {
            int i = t + r*128;
            int kk = i >> 5, j = i & 31;
            float kv = g_K[(size_t)(b*TK + kt + kk)*DD + h*DK + j];
            *(float2*)&Ksd[kk][2*j] = make_float2(kv, kv);
        }
        // Cs fill: 32k x 9 float4-groups over f
        for (int i = t; i < 288; i += 128) {
            int k = i / 9;
            int c4 = (i - k*9) * 4;
            size_t base = (size_t)(b*TK + kt + k)*FF + c4;
            float4 mm = *(const float4*)(mask + base);
            float4 vv = *(const float4*)(value + base);
#pragma unroll
            for (int u = 0; u < 4; ++u) {
                int f = c4 + u;
                int g = f / 9, ii = f - g*9;
                float m = (&mm.x)[u], v = (&vv.x)[u];
                Cs[k][g][2*ii]   = m * v;
                Cs[k][g][2*ii+1] = m;
            }
        }
        __syncthreads();

        // ---- Phase A: thread owns kk = kkA, computes 16 q's (qq4*16..+15)
        {
            float2 acc2[8];
#pragma unroll
            for (int p = 0; p < 8; ++p) acc2[p] = make_float2(0.f, 0.f);
#pragma unroll
            for (int jc = 0; jc < 4; ++jc) {      // 8 j at a time (reg-lean)
                float2 kr2[8];
#pragma unroll
                for (int j = 0; j < 8; ++j)
                    kr2[j] = *(const float2*)&Ksd[kkA][2*(jc*8 + j)];
#pragma unroll
                for (int j = 0; j < 8; ++j) {
                    const float4* qp = (const float4*)&Qst[jc*8 + j][qq4*16];
#pragma unroll
                    for (int c = 0; c < 4; ++c) {
                        float4 qv = qp[c];
                        acc2[2*c]   = fma2(*(const float2*)&qv.x, kr2[j], acc2[2*c]);
                        acc2[2*c+1] = fma2(*(const float2*)&qv.z, kr2[j], acc2[2*c+1]);
                    }
                }
            }
#pragma unroll
            for (int c = 0; c < 4; ++c) {
                float4 ev;
                ev.x = __expf(fminf(acc2[2*c].x,   80.f));
                ev.y = __expf(fminf(acc2[2*c].y,   80.f));
                ev.z = __expf(fminf(acc2[2*c+1].x, 80.f));
                ev.w = __expf(fminf(acc2[2*c+1].y, 80.f));
                *(float4*)&Es[kkA][qq4*16 + 4*c] = ev;
            }
        }
        __syncthreads();

        // ---- Phase B: accumulate num/den (no temp arrays)
#pragma unroll 4
        for (int kk = 0; kk < 32; ++kk) {
            float2 e2 = *(const float2*)&Es[kk][qg*2];
            float2 e0 = dup2(e2.x), e1 = dup2(e2.y);
            const float4* cp = (const float4*)&Cs[kk][fg][0];
            float4 c0 = cp[0], c1 = cp[1], c2 = cp[2], c3 = cp[3], c4v = cp[4];
            nd[0][0] = fma2(e0, *(const float2*)&c0.x,  nd[0][0]);
            nd[1][0] = fma2(e1, *(const float2*)&c0.x,  nd[1][0]);
            nd[0][1] = fma2(e0, *(const float2*)&c0.z,  nd[0][1]);
            nd[1][1] = fma2(e1, *(const float2*)&c0.z,  nd[1][1]);
            nd[0][2] = fma2(e0, *(const float2*)&c1.x,  nd[0][2]);
            nd[1][2] = fma2(e1, *(const float2*)&c1.x,  nd[1][2]);
            nd[0][3] = fma2(e0, *(const float2*)&c1.z,  nd[0][3]);
            nd[1][3] = fma2(e1, *(const float2*)&c1.z,  nd[1][3]);
            nd[0][4] = fma2(e0, *(const float2*)&c2.x,  nd[0][4]);
            nd[1][4] = fma2(e1, *(const float2*)&c2.x,  nd[1][4]);
            nd[0][5] = fma2(e0, *(const float2*)&c2.z,  nd[0][5]);
            nd[1][5] = fma2(e1, *(const float2*)&c2.z,  nd[1][5]);
            nd[0][6] = fma2(e0, *(const float2*)&c3.x,  nd[0][6]);
            nd[1][6] = fma2(e1, *(const float2*)&c3.x,  nd[1][6]);
            nd[0][7] = fma2(e0, *(const float2*)&c3.z,  nd[0][7]);
            nd[1][7] = fma2(e1, *(const float2*)&c3.z,  nd[1][7]);
            nd[0][8] = fma2(e0, *(const float2*)&c4v.x, nd[0][8]);
            nd[1][8] = fma2(e1, *(const float2*)&c4v.x, nd[1][8]);
        }
    }

#pragma unroll
    for (int qq = 0; qq < 2; ++qq) {
        int q = q0 + qg*2 + qq;
        float* o = g_HN + (size_t)(b*TQ + q)*FF*HH + h;
#pragma unroll
        for (int i = 0; i < 9; ++i) {
            int f = fg*9 + i;
            o[(size_t)f*HH] = __fdividef(nd[qq][i].x, nd[qq][i].y);
        }
    }
}

// ---------------------------------------------------------------------------
// Kernel 3: fused epilogue. Block = 2 (b,q) rows; 64 threads per row; thread
// owns 4 d's. Smem operands NON-dup (crossbar bytes halved); dup via MOVs.
// ---------------------------------------------------------------------------
__global__ void __launch_bounds__(128) epilogue_kernel(
        const float* __restrict__ Wc,  const float* __restrict__ bc,
        const float* __restrict__ Wo1, const float* __restrict__ bo1,
        const float* __restrict__ Wo2, const float* __restrict__ bo2,
        float* __restrict__ out) {
    int t    = threadIdx.x;
    int half = t >> 6;           // which bq of the pair
    int u    = t & 63;           // d base
    int bq   = 2*blockIdx.x + half;

    __shared__ __align__(16) float hs[2][FF*HH];    // plain, per bq (288 each)
    __shared__ __align__(16) float w1s[FF*SFD + 8]; // plain (216)

    const float* hn0 = g_HN + (size_t)(2*blockIdx.x)*FF*HH;
    for (int i = t; i < 144; i += 128)              // flat copy: 144 float4
        ((float4*)hs)[i] = *(const float4*)(hn0 + 4*i);
    if (t < 54)
        ((float4*)w1s)[t] = *(const float4*)(Wo1 + 4*t);
    __syncthreads();

    int d0 = u, d1 = u + 64, d2 = u + 128, d3 = u + 192;
    float2 wcA[HH], wcB[HH];
#pragma unroll
    for (int h = 0; h < HH; ++h) {
        wcA[h] = make_float2(Wc[h*DD + d0], Wc[h*DD + d1]);
        wcB[h] = make_float2(Wc[h*DD + d2], Wc[h*DD + d3]);
    }
    float2 bcA = make_float2(bc[d0], bc[d1]);
    float2 bcB = make_float2(bc[d2], bc[d3]);

    float2 accA[SFD], accB[SFD];
#pragma unroll
    for (int s = 0; s < SFD; ++s) { accA[s] = dup2(bo1[s]); accB[s] = dup2(bo1[s]); }

    const float* hbase = &hs[half][0];
#pragma unroll 4
    for (int f = 0; f < FF; ++f) {
        float4 h0 = *(const float4*)&hbase[f*HH];       // h = 0..3
        float4 h1 = *(const float4*)&hbase[f*HH + 4];   // h = 4..7
        float2 aA = bcA, aB = bcB;
        {
            float2 dh;
            dh = dup2(h0.x); aA = fma2(dh, wcA[0], aA); aB = fma2(dh, wcB[0], aB);
            dh = dup2(h0.y); aA = fma2(dh, wcA[1], aA); aB = fma2(dh, wcB[1], aB);
            dh = dup2(h0.z); aA = fma2(dh, wcA[2], aA); aB = fma2(dh, wcB[2], aB);
            dh = dup2(h0.w); aA = fma2(dh, wcA[3], aA); aB = fma2(dh, wcB[3], aB);
            dh = dup2(h1.x); aA = fma2(dh, wcA[4], aA); aB = fma2(dh, wcB[4], aB);
            dh = dup2(h1.y); aA = fma2(dh, wcA[5], aA); aB = fma2(dh, wcB[5], aB);
            dh = dup2(h1.z); aA = fma2(dh, wcA[6], aA); aB = fma2(dh, wcB[6], aB);
            dh = dup2(h1.w); aA = fma2(dh, wcA[7], aA); aB = fma2(dh, wcB[7], aB);
        }
        float2 latA = tanh2(aA), latB = tanh2(aB);
#pragma unroll
        for (int j = 0; j < 3; ++j) {
            float2 wpair = *(const float2*)&w1s[f*SFD + 2*j];   // s = 2j, 2j+1
            float2 wlo = dup2(wpair.x), whi = dup2(wpair.y);
            accA[2*j]   = fma2(latA, wlo, accA[2*j]);
            accA[2*j+1] = fma2(latA, whi, accA[2*j+1]);
            accB[2*j]   = fma2(latB, wlo, accB[2*j]);
            accB[2*j+1] = fma2(latB, whi, accB[2*j+1]);
        }
    }

    float2 resA = make_float2(bo2[d0], bo2[d1]);
    float2 resB = make_float2(bo2[d2], bo2[d3]);
#pragma unroll
    for (int s = 0; s < SFD; ++s) {
        float2 w2 = dup2(Wo2[s]);
        resA = fma2(tanh2(accA[s]), w2, resA);
        resB = fma2(tanh2(accB[s]), w2, resB);
    }

    float* o = out + (size_t)bq*DD;
    o[d0] = resA.x; o[d1] = resA.y;
    o[d2] = resB.x; o[d3] = resB.y;
}

// ---------------------------------------------------------------------------
extern "C" void kernel_launch(void* const* d_in, const int* in_sizes, int n_in,
                              void* d_out, int out_size) {
    const float* query = (const float*)d_in[0];
    const float* key   = (const float*)d_in[1];
    const float* value = (const float*)d_in[2];
    const float* mask  = (const float*)d_in[3];
    const float* Wq    = (const float*)d_in[4];
    const float* Wk    = (const float*)d_in[5];
    const float* Wc    = (const float*)d_in[6];
    const float* bc    = (const float*)d_in[7];
    const float* Wo1   = (const float*)d_in[8];
    const float* bo1   = (const float*)d_in[9];
    const float* Wo2   = (const float*)d_in[10];
    const float* bo2   = (const float*)d_in[11];
    float* out = (float*)d_out;

    proj_kernel<<<dim3(NB*TQ/PM, DD/PN, 2), 256>>>(query, key, Wq, Wk);
    fused_attn_kernel<<<dim3(NB, HH, 4), 128>>>(value, mask);
    epilogue_kernel<<<NB*TQ/2, 128>>>(Wc, bc, Wo1, bo1, Wo2, bo2, out);
}